// round 6
// baseline (speedup 1.0000x reference)
#include <cuda_runtime.h>
#include <cuda_bf16.h>
#include <cstdint>

// Problem constants
#define BB 2
#define SS 2048
#define DD 1024
#define HH 16
#define HD 64
#define D3 3072
#define MROWS (BB * SS)          // 4096
#define SCALE 0.03125f           // 1/sqrt(1024)
#define LOG2E 1.4426950408889634f
#define LN_EPS 1e-5f

// ---------------------------------------------------------------------------
// Scratch (no allocation allowed -> __device__ globals)
// ---------------------------------------------------------------------------
__device__ float g_qkv[MROWS * D3];     // 48 MB (tf32-rounded values)
__device__ float g_o[MROWS * DD];       // 16 MB (attention out, tf32-rounded)
__device__ float g_y[MROWS * DD];       // 16 MB (proj + residual, fp32)
__device__ float g_xr[MROWS * DD];      // 16 MB (x, tf32-rounded)
__device__ float g_wr[D3 * DD];         // 12 MB (W_w, tf32-rounded)
__device__ float g_pwr[DD * DD];        //  4 MB (proj_w, tf32-rounded)

// ---------------------------------------------------------------------------
// Portable helpers (sm_80+ only)
// ---------------------------------------------------------------------------
__device__ __forceinline__ uint32_t smem_u32(const void* p) {
    uint32_t a;
    asm("{ .reg .u64 t; cvta.to.shared.u64 t, %1; cvt.u32.u64 %0, t; }"
        : "=r"(a) : "l"(p));
    return a;
}

__device__ __forceinline__ void cp16(uint32_t dst, const void* src) {
    asm volatile("cp.async.cg.shared.global [%0], [%1], 16;"
                 :: "r"(dst), "l"(src) : "memory");
}
#define CP_COMMIT() asm volatile("cp.async.commit_group;" ::: "memory")
#define CP_WAIT1()  asm volatile("cp.async.wait_group 1;" ::: "memory")
#define CP_WAIT0()  asm volatile("cp.async.wait_group 0;" ::: "memory")

__device__ __forceinline__ uint32_t f2tf(float f) {
    uint32_t r;
    asm("cvt.rna.tf32.f32 %0, %1;" : "=r"(r) : "f"(f));
    return r;
}
__device__ __forceinline__ float roundtf(float f) {
    return __uint_as_float(f2tf(f));
}

__device__ __forceinline__ float ex2f(float x) {
    float r;
    asm("ex2.approx.f32 %0, %1;" : "=f"(r) : "f"(x));
    return r;
}

__device__ __forceinline__ void mma_tf32(
    float* c, const uint32_t* a, const uint32_t* b)
{
    asm volatile(
        "mma.sync.aligned.m16n8k8.row.col.f32.tf32.tf32.f32 "
        "{%0,%1,%2,%3}, {%4,%5,%6,%7}, {%8,%9}, {%0,%1,%2,%3};"
        : "+f"(c[0]), "+f"(c[1]), "+f"(c[2]), "+f"(c[3])
        : "r"(a[0]), "r"(a[1]), "r"(a[2]), "r"(a[3]),
          "r"(b[0]), "r"(b[1]));
}

// ---------------------------------------------------------------------------
// Pre-round fp32 -> tf32-rounded fp32
// ---------------------------------------------------------------------------
__global__ __launch_bounds__(256) void round_tf32_k(
    const float* __restrict__ in, float* __restrict__ out, int n4)
{
    const int i = blockIdx.x * 256 + threadIdx.x;
    if (i < n4) {
        float4 v = *(const float4*)(in + (size_t)i * 4);
        v.x = roundtf(v.x); v.y = roundtf(v.y);
        v.z = roundtf(v.z); v.w = roundtf(v.w);
        *(float4*)(out + (size_t)i * 4) = v;
    }
}

// ===========================================================================
// TF32 mma.sync GEMM: C[M,N] = A[M,K] @ W[N,K]^T + bias (+ resid)
// A, W tf32-pre-rounded (raw-bit fragments). CTA 128x128, BK=32, 8 warps.
// Warp-parity-staggered slice order to spread LDS/MMA bursts.
// ===========================================================================
#define GK 32
#define GPAD 36
#define GTILE_FLOATS (128 * GPAD)
#define GTILE_BYTES  (GTILE_FLOATS * 4)
#define GEMM_SMEM    (4 * GTILE_BYTES)            // 73728

__global__ __launch_bounds__(256) void gemm_tf32(
    const float* __restrict__ A, const float* __restrict__ W,
    const float* __restrict__ bias, const float* __restrict__ resid,
    float* __restrict__ C, int M, int N, int K, int round_out)
{
    extern __shared__ float sm[];
    float* As[2] = { sm,                  sm + GTILE_FLOATS };
    float* Bs[2] = { sm + 2*GTILE_FLOATS, sm + 3*GTILE_FLOATS };
    const uint32_t sA[2] = { smem_u32(As[0]), smem_u32(As[1]) };
    const uint32_t sB[2] = { smem_u32(Bs[0]), smem_u32(Bs[1]) };

    const int tid  = threadIdx.x;
    const int lane = tid & 31;
    const int wid  = tid >> 5;
    const int g    = lane >> 2;
    const int c    = lane & 3;
    const int wm0  = (wid & 3) * 32;
    const int wn0  = (wid >> 2) * 64;
    const int m0   = blockIdx.y * 128;
    const int n0   = blockIdx.x * 128;
    const int kks  = (wid & 1) * 16;     // stagger offset per warp parity

    float acc[2][8][4];
#pragma unroll
    for (int mt = 0; mt < 2; mt++)
#pragma unroll
        for (int nt = 0; nt < 8; nt++)
#pragma unroll
            for (int k = 0; k < 4; k++) acc[mt][nt][k] = 0.f;

    const int nch = K >> 5;

    auto load_chunk = [&](int i, int st) {
        const float* Ag = A + (size_t)m0 * K + i * GK;
        const float* Wg = W + (size_t)n0 * K + i * GK;
#pragma unroll
        for (int t = 0; t < 4; t++) {
            const int idx = tid + t * 256;
            const int row = idx >> 3;
            const int q   = idx & 7;
            const uint32_t off = (uint32_t)(row * GPAD + q * 4) * 4u;
            cp16(sA[st] + off, Ag + (size_t)row * K + q * 4);
            cp16(sB[st] + off, Wg + (size_t)row * K + q * 4);
        }
        CP_COMMIT();
    };

    load_chunk(0, 0);

    for (int i = 0; i < nch; i++) {
        const int st = i & 1;
        if (i + 1 < nch) { load_chunk(i + 1, st ^ 1); CP_WAIT1(); }
        else             { CP_WAIT0(); }
        __syncthreads();

        const uint32_t* Af = (const uint32_t*)As[st];
        const uint32_t* Bf = (const uint32_t*)Bs[st];
#pragma unroll
        for (int s = 0; s < 4; s++) {
            const int kk = (kks + s * 8) & 31;
            uint32_t af[2][4];
#pragma unroll
            for (int mt = 0; mt < 2; mt++) {
                const int m = wm0 + mt * 16 + g;
                af[mt][0] = Af[(m    ) * GPAD + kk + c    ];
                af[mt][1] = Af[(m + 8) * GPAD + kk + c    ];
                af[mt][2] = Af[(m    ) * GPAD + kk + c + 4];
                af[mt][3] = Af[(m + 8) * GPAD + kk + c + 4];
            }
            uint32_t bf[8][2];
#pragma unroll
            for (int nt = 0; nt < 8; nt++) {
                const int n = wn0 + nt * 8 + g;
                bf[nt][0] = Bf[n * GPAD + kk + c    ];
                bf[nt][1] = Bf[n * GPAD + kk + c + 4];
            }
#pragma unroll
            for (int mt = 0; mt < 2; mt++)
#pragma unroll
                for (int nt = 0; nt < 8; nt++)
                    mma_tf32(acc[mt][nt], af[mt], bf[nt]);
        }
        __syncthreads();
    }

#pragma unroll
    for (int mt = 0; mt < 2; mt++) {
#pragma unroll
        for (int hrow = 0; hrow < 2; hrow++) {
            const int m = m0 + wm0 + mt * 16 + g + hrow * 8;
#pragma unroll
            for (int nt = 0; nt < 8; nt++) {
                const int col = n0 + wn0 + nt * 8 + c * 2;
                float2 bi = *(const float2*)(bias + col);
                float2 v;
                v.x = acc[mt][nt][hrow * 2 + 0] + bi.x;
                v.y = acc[mt][nt][hrow * 2 + 1] + bi.y;
                if (resid) {
                    float2 r = *(const float2*)(resid + (size_t)m * N + col);
                    v.x += r.x; v.y += r.y;
                }
                if (round_out) { v.x = roundtf(v.x); v.y = roundtf(v.y); }
                *(float2*)(C + (size_t)m * N + col) = v;
            }
        }
    }
}

// ===========================================================================
// Tensor-core flash attention, 256 threads, Q-tile 128 x 64-wide K tiles.
// Block (qtx,h,b), qt = 15 - qtx (heavy CTAs first). 8 warps x 16 q-rows.
// ===========================================================================
#define QS_STR 68
#define VS_STR 72
#define KS_OFF  (128 * QS_STR)                 // 8704 floats (after Q/P tile)
#define VS_OFF  (KS_OFF + 2 * 64 * QS_STR)     // 17408
#define BI_OFF  (VS_OFF + 2 * 64 * VS_STR)     // 26624
#define ATTN_SMEM ((BI_OFF + 2 * 192) * 4)     // 108032 bytes

__global__ __launch_bounds__(256) void attn_mma(
    const float* __restrict__ qkv, const float* __restrict__ rpb,
    float* __restrict__ obuf)
{
    extern __shared__ float smf[];
    const uint32_t sbase = smem_u32(smf);
    float* Qs = smf;                     // 128 x QS_STR, reused as P tile
    uint32_t* PsU = (uint32_t*)Qs;

    const int qt = 15 - blockIdx.x;      // descending work order
    const int h  = blockIdx.y;
    const int b  = blockIdx.z;
    const int tid = threadIdx.x;
    const int w    = tid >> 5;
    const int lane = tid & 31;
    const int g    = lane >> 2;
    const int c    = lane & 3;
    const int q0   = qt * 128;
    const int r0   = w * 16 + g;         // tile-local q row (0..127)
    const int r1   = r0 + 8;

    // ---- Load Q tile (pre-scaled) ----
    const float CF = SCALE * LOG2E;
#pragma unroll
    for (int t = 0; t < 8; t++) {
        const int idx = tid + t * 256;
        const int r = idx >> 4, q = idx & 15;
        float4 v = *(const float4*)(qkv + (size_t)(b * SS + q0 + r) * D3 + h * HD + q * 4);
        v.x *= CF; v.y *= CF; v.z *= CF; v.w *= CF;
        *(float4*)(Qs + r * QS_STR + q * 4) = v;
    }
    __syncthreads();

    // ---- Extract Q fragments ----
    uint32_t aq[8][4];
#pragma unroll
    for (int kk = 0; kk < 8; kk++) {
        const int col = kk * 8 + c;
        aq[kk][0] = f2tf(Qs[r0 * QS_STR + col    ]);
        aq[kk][1] = f2tf(Qs[r1 * QS_STR + col    ]);
        aq[kk][2] = f2tf(Qs[r0 * QS_STR + col + 4]);
        aq[kk][3] = f2tf(Qs[r1 * QS_STR + col + 4]);
    }
    __syncthreads();   // Qs becomes the P tile

    float m0 = -1e30f, m1 = -1e30f, l0 = 0.f, l1 = 0.f;
    float o[8][4];
#pragma unroll
    for (int nt = 0; nt < 8; nt++)
#pragma unroll
        for (int k = 0; k < 4; k++) o[nt][k] = 0.f;

    auto loadKV = [&](int kt, int st) {
        const float* Kg = qkv + (size_t)(b * SS + kt * 64) * D3 + DD + h * HD;
        const float* Vg = qkv + (size_t)(b * SS + kt * 64) * D3 + 2 * DD + h * HD;
        const uint32_t kbase = sbase + (KS_OFF + st * 64 * QS_STR) * 4u;
        const uint32_t vbase = sbase + (VS_OFF + st * 64 * VS_STR) * 4u;
#pragma unroll
        for (int t = 0; t < 4; t++) {
            const int idx = tid + t * 256;
            const int r = idx >> 4, q = idx & 15;
            cp16(kbase + (uint32_t)(r * QS_STR + q * 4) * 4u, Kg + (size_t)r * D3 + q * 4);
            cp16(vbase + (uint32_t)(r * VS_STR + q * 4) * 4u, Vg + (size_t)r * D3 + q * 4);
        }
        if (tid < 192) {
            const int delta = tid - 127 + kt * 64 - q0;
            smf[BI_OFF + st * 192 + tid] = rpb[(size_t)(delta + SS - 1) * HH + h] * LOG2E;
        }
        CP_COMMIT();
    };

    const int ktmax = 2 * qt + 1;
    loadKV(0, 0);

    for (int kt = 0; kt <= ktmax; kt++) {
        const int st = kt & 1;
        if (kt < ktmax) { loadKV(kt + 1, st ^ 1); CP_WAIT1(); }
        else            { CP_WAIT0(); }
        __syncthreads();

        const uint32_t* KsU = (const uint32_t*)(smf + KS_OFF + st * 64 * QS_STR);
        const uint32_t* VsU = (const uint32_t*)(smf + VS_OFF + st * 64 * VS_STR);
        const float* bsp = smf + BI_OFF + st * 192;
        const bool domask = (kt >= 2 * qt);
        const int joff = kt * 64 - q0;

        // ---- S = Qhat @ K^T ----
        float s[8][4];
#pragma unroll
        for (int nt = 0; nt < 8; nt++)
#pragma unroll
            for (int k = 0; k < 4; k++) s[nt][k] = 0.f;

#pragma unroll
        for (int kk = 0; kk < 8; kk++) {
            uint32_t bf[8][2];
#pragma unroll
            for (int nt = 0; nt < 8; nt++) {
                const int n = nt * 8 + g;
                bf[nt][0] = KsU[n * QS_STR + kk * 8 + c    ];
                bf[nt][1] = KsU[n * QS_STR + kk * 8 + c + 4];
            }
#pragma unroll
            for (int nt = 0; nt < 8; nt++)
                mma_tf32(s[nt], aq[kk], bf[nt]);
        }

        // ---- bias + causal mask + tile max ----
        float tm0 = -1e30f, tm1 = -1e30f;
#pragma unroll
        for (int nt = 0; nt < 8; nt++) {
            const int col = nt * 8 + c * 2;
            s[nt][0] += bsp[col     - r0 + 127];
            s[nt][1] += bsp[col + 1 - r0 + 127];
            s[nt][2] += bsp[col     - r1 + 127];
            s[nt][3] += bsp[col + 1 - r1 + 127];
            if (domask) {
                if (col     + joff > r0) s[nt][0] = -1e30f;
                if (col + 1 + joff > r0) s[nt][1] = -1e30f;
                if (col     + joff > r1) s[nt][2] = -1e30f;
                if (col + 1 + joff > r1) s[nt][3] = -1e30f;
            }
            tm0 = fmaxf(tm0, fmaxf(s[nt][0], s[nt][1]));
            tm1 = fmaxf(tm1, fmaxf(s[nt][2], s[nt][3]));
        }
        tm0 = fmaxf(tm0, __shfl_xor_sync(0xffffffffu, tm0, 1));
        tm0 = fmaxf(tm0, __shfl_xor_sync(0xffffffffu, tm0, 2));
        tm1 = fmaxf(tm1, __shfl_xor_sync(0xffffffffu, tm1, 1));
        tm1 = fmaxf(tm1, __shfl_xor_sync(0xffffffffu, tm1, 2));

        const float mn0 = fmaxf(m0, tm0);
        const float mn1 = fmaxf(m1, tm1);
        const float alpha0 = ex2f(m0 - mn0);
        const float alpha1 = ex2f(m1 - mn1);
        m0 = mn0; m1 = mn1;

        // ---- P = 2^(s - m); tf32 bits to smem; row sums ----
        float sum0 = 0.f, sum1 = 0.f;
#pragma unroll
        for (int nt = 0; nt < 8; nt++) {
            const int col = nt * 8 + c * 2;
            float p0 = ex2f(s[nt][0] - mn0);
            float p1 = ex2f(s[nt][1] - mn0);
            float p2 = ex2f(s[nt][2] - mn1);
            float p3 = ex2f(s[nt][3] - mn1);
            sum0 += p0 + p1;
            sum1 += p2 + p3;
            *(uint2*)&PsU[r0 * QS_STR + col] = make_uint2(f2tf(p0), f2tf(p1));
            *(uint2*)&PsU[r1 * QS_STR + col] = make_uint2(f2tf(p2), f2tf(p3));
        }
        sum0 += __shfl_xor_sync(0xffffffffu, sum0, 1);
        sum0 += __shfl_xor_sync(0xffffffffu, sum0, 2);
        sum1 += __shfl_xor_sync(0xffffffffu, sum1, 1);
        sum1 += __shfl_xor_sync(0xffffffffu, sum1, 2);
        l0 = l0 * alpha0 + sum0;
        l1 = l1 * alpha1 + sum1;

#pragma unroll
        for (int nt = 0; nt < 8; nt++) {
            o[nt][0] *= alpha0; o[nt][1] *= alpha0;
            o[nt][2] *= alpha1; o[nt][3] *= alpha1;
        }
        __syncwarp();

        // ---- O += P @ V (V raw bits, transposed read) ----
#pragma unroll
        for (int kk = 0; kk < 8; kk++) {
            uint32_t ap[4];
            ap[0] = PsU[r0 * QS_STR + kk * 8 + c    ];
            ap[1] = PsU[r1 * QS_STR + kk * 8 + c    ];
            ap[2] = PsU[r0 * QS_STR + kk * 8 + c + 4];
            ap[3] = PsU[r1 * QS_STR + kk * 8 + c + 4];
            uint32_t bv[8][2];
#pragma unroll
            for (int nt = 0; nt < 8; nt++) {
                const int n = nt * 8 + g;
                bv[nt][0] = VsU[(kk * 8 + c    ) * VS_STR + n];
                bv[nt][1] = VsU[(kk * 8 + c + 4) * VS_STR + n];
            }
#pragma unroll
            for (int nt = 0; nt < 8; nt++)
                mma_tf32(o[nt], ap, bv[nt]);
        }
        __syncthreads();
    }

    // ---- Normalize + write (tf32-rounded for proj GEMM) ----
    const float inv0 = 1.f / l0;
    const float inv1 = 1.f / l1;
    const size_t base0 = (size_t)(b * SS + q0 + r0) * DD + h * HD;
    const size_t base1 = (size_t)(b * SS + q0 + r1) * DD + h * HD;
#pragma unroll
    for (int nt = 0; nt < 8; nt++) {
        const int col = nt * 8 + c * 2;
        *(float2*)(obuf + base0 + col) =
            make_float2(roundtf(o[nt][0] * inv0), roundtf(o[nt][1] * inv0));
        *(float2*)(obuf + base1 + col) =
            make_float2(roundtf(o[nt][2] * inv1), roundtf(o[nt][3] * inv1));
    }
}

// ---------------------------------------------------------------------------
// LayerNorm over D=1024
// ---------------------------------------------------------------------------
__global__ __launch_bounds__(256) void layernorm_k(
    const float* __restrict__ y, const float* __restrict__ g,
    const float* __restrict__ bta, float* __restrict__ out)
{
    const int row = blockIdx.x;
    const int t = threadIdx.x;
    const float4 v = *(const float4*)(y + (size_t)row * DD + t * 4);

    float s  = v.x + v.y + v.z + v.w;
    float sq = v.x * v.x + v.y * v.y + v.z * v.z + v.w * v.w;
#pragma unroll
    for (int off = 16; off > 0; off >>= 1) {
        s  += __shfl_xor_sync(0xffffffffu, s, off);
        sq += __shfl_xor_sync(0xffffffffu, sq, off);
    }
    __shared__ float ss[8], sqq[8];
    if ((t & 31) == 0) { ss[t >> 5] = s; sqq[t >> 5] = sq; }
    __syncthreads();
    float tot = 0.f, totq = 0.f;
#pragma unroll
    for (int i = 0; i < 8; i++) { tot += ss[i]; totq += sqq[i]; }
    const float mu  = tot * (1.f / DD);
    const float var = totq * (1.f / DD) - mu * mu;
    const float r   = rsqrtf(var + LN_EPS);

    const float4 gg = *(const float4*)(g + t * 4);
    const float4 bb = *(const float4*)(bta + t * 4);
    float4 o4;
    o4.x = (v.x - mu) * r * gg.x + bb.x;
    o4.y = (v.y - mu) * r * gg.y + bb.y;
    o4.z = (v.z - mu) * r * gg.z + bb.z;
    o4.w = (v.w - mu) * r * gg.w + bb.w;
    *(float4*)(out + (size_t)row * DD + t * 4) = o4;
}

// ---------------------------------------------------------------------------
// Launch
// ---------------------------------------------------------------------------
extern "C" void kernel_launch(void* const* d_in, const int* in_sizes, int n_in,
                              void* d_out, int out_size)
{
    const float* x      = (const float*)d_in[0];
    const float* W_w    = (const float*)d_in[1];
    const float* W_b    = (const float*)d_in[2];
    const float* proj_w = (const float*)d_in[3];
    const float* proj_b = (const float*)d_in[4];
    const float* ln_g   = (const float*)d_in[5];
    const float* ln_b   = (const float*)d_in[6];
    const float* rpb    = (const float*)d_in[7];
    float* out = (float*)d_out;

    float *qkv, *obuf, *ybuf, *xr, *wr, *pwr;
    cudaGetSymbolAddress((void**)&qkv,  g_qkv);
    cudaGetSymbolAddress((void**)&obuf, g_o);
    cudaGetSymbolAddress((void**)&ybuf, g_y);
    cudaGetSymbolAddress((void**)&xr,   g_xr);
    cudaGetSymbolAddress((void**)&wr,   g_wr);
    cudaGetSymbolAddress((void**)&pwr,  g_pwr);

    cudaFuncSetAttribute(gemm_tf32, cudaFuncAttributeMaxDynamicSharedMemorySize, GEMM_SMEM);
    cudaFuncSetAttribute(attn_mma, cudaFuncAttributeMaxDynamicSharedMemorySize, ATTN_SMEM);

    // 0) Pre-round inputs to tf32 values
    round_tf32_k<<<(MROWS * DD / 4 + 255) / 256, 256>>>(x, xr, MROWS * DD / 4);
    round_tf32_k<<<(D3 * DD / 4 + 255) / 256, 256>>>(W_w, wr, D3 * DD / 4);
    round_tf32_k<<<(DD * DD / 4 + 255) / 256, 256>>>(proj_w, pwr, DD * DD / 4);

    // 1) QKV projection (outputs rounded for attention)
    {
        dim3 grid(D3 / 128, MROWS / 128);
        gemm_tf32<<<grid, 256, GEMM_SMEM>>>(xr, wr, W_b, nullptr, qkv, MROWS, D3, DD, 1);
    }

    // 2) Flash attention (256 threads, 128-row Q tiles)
    {
        dim3 grid(SS / 128, HH, BB);
        attn_mma<<<grid, 256, ATTN_SMEM>>>(qkv, rpb, obuf);
    }

    // 3) Output projection + residual
    {
        dim3 grid(DD / 128, MROWS / 128);
        gemm_tf32<<<grid, 256, GEMM_SMEM>>>(obuf, pwr, proj_b, x, ybuf, MROWS, DD, DD, 0);
    }

    // 4) LayerNorm
    layernorm_k<<<MROWS, 256>>>(ybuf, ln_g, ln_b, out);
}

// round 7
// speedup vs baseline: 1.6149x; 1.6149x over previous
#include <cuda_runtime.h>
#include <cuda_bf16.h>
#include <cstdint>

// Problem constants
#define BB 2
#define SS 2048
#define DD 1024
#define HH 16
#define HD 64
#define D3 3072
#define MROWS (BB * SS)          // 4096
#define SCALE 0.03125f           // 1/sqrt(1024)
#define LOG2E 1.4426950408889634f
#define LN_EPS 1e-5f

// ---------------------------------------------------------------------------
// Scratch (no allocation allowed -> __device__ globals)
// ---------------------------------------------------------------------------
__device__ float g_qkv[MROWS * D3];            // 48 MB (tf32-rounded fp32)
__device__ float g_y[MROWS * DD];              // 16 MB (proj + residual, fp32)
__device__ __nv_bfloat16 g_xb[MROWS * DD];     //  8 MB (x, bf16)
__device__ __nv_bfloat16 g_wb[D3 * DD];        //  6 MB (W_w, bf16)
__device__ __nv_bfloat16 g_pwb[DD * DD];       //  2 MB (proj_w, bf16)
__device__ __nv_bfloat16 g_ob[MROWS * DD];     //  8 MB (attention out, bf16)

// ---------------------------------------------------------------------------
// Portable helpers (sm_80+ only)
// ---------------------------------------------------------------------------
__device__ __forceinline__ uint32_t smem_u32(const void* p) {
    uint32_t a;
    asm("{ .reg .u64 t; cvta.to.shared.u64 t, %1; cvt.u32.u64 %0, t; }"
        : "=r"(a) : "l"(p));
    return a;
}

__device__ __forceinline__ void cp16(uint32_t dst, const void* src) {
    asm volatile("cp.async.ca.shared.global [%0], [%1], 16;"
                 :: "r"(dst), "l"(src) : "memory");
}
#define CP_COMMIT() asm volatile("cp.async.commit_group;" ::: "memory")
#define CP_WAIT1()  asm volatile("cp.async.wait_group 1;" ::: "memory")
#define CP_WAIT0()  asm volatile("cp.async.wait_group 0;" ::: "memory")

__device__ __forceinline__ uint32_t f2tf(float f) {
    uint32_t r;
    asm("cvt.rna.tf32.f32 %0, %1;" : "=r"(r) : "f"(f));
    return r;
}
__device__ __forceinline__ float roundtf(float f) {
    return __uint_as_float(f2tf(f));
}

__device__ __forceinline__ float ex2f(float x) {
    float r;
    asm("ex2.approx.f32 %0, %1;" : "=f"(r) : "f"(x));
    return r;
}

__device__ __forceinline__ void mma_tf32(
    float* c, const uint32_t* a, const uint32_t* b)
{
    asm volatile(
        "mma.sync.aligned.m16n8k8.row.col.f32.tf32.tf32.f32 "
        "{%0,%1,%2,%3}, {%4,%5,%6,%7}, {%8,%9}, {%0,%1,%2,%3};"
        : "+f"(c[0]), "+f"(c[1]), "+f"(c[2]), "+f"(c[3])
        : "r"(a[0]), "r"(a[1]), "r"(a[2]), "r"(a[3]),
          "r"(b[0]), "r"(b[1]));
}

__device__ __forceinline__ void mma_bf16(
    float* c, const uint32_t* a, uint32_t b0, uint32_t b1)
{
    asm volatile(
        "mma.sync.aligned.m16n8k16.row.col.f32.bf16.bf16.f32 "
        "{%0,%1,%2,%3}, {%4,%5,%6,%7}, {%8,%9}, {%0,%1,%2,%3};"
        : "+f"(c[0]), "+f"(c[1]), "+f"(c[2]), "+f"(c[3])
        : "r"(a[0]), "r"(a[1]), "r"(a[2]), "r"(a[3]),
          "r"(b0), "r"(b1));
}

#define LDSM4(r0, r1, r2, r3, addr) \
    asm volatile("ldmatrix.sync.aligned.m8n8.x4.shared.b16 {%0,%1,%2,%3}, [%4];" \
        : "=r"(r0), "=r"(r1), "=r"(r2), "=r"(r3) : "r"(addr))

// ---------------------------------------------------------------------------
// fp32 -> bf16 conversion (vectorized)
// ---------------------------------------------------------------------------
__global__ __launch_bounds__(256) void cvt_bf16_k(
    const float* __restrict__ in, __nv_bfloat16* __restrict__ out, int n4)
{
    const int i = blockIdx.x * 256 + threadIdx.x;
    if (i < n4) {
        float4 v = *(const float4*)(in + (size_t)i * 4);
        __nv_bfloat162 lo = __floats2bfloat162_rn(v.x, v.y);
        __nv_bfloat162 hi = __floats2bfloat162_rn(v.z, v.w);
        uint2 u;
        u.x = *(uint32_t*)&lo;
        u.y = *(uint32_t*)&hi;
        *(uint2*)(out + (size_t)i * 4) = u;
    }
}

// ===========================================================================
// BF16 mma.sync GEMM: C[M,N] = A[M,K] @ W[N,K]^T + bias (+ resid)
// A, W bf16. CTA 128x128, BK=64, 8 warps (4M x 2N), warp tile 32x64.
// ldmatrix.x4 fragment loads, 144B smem row stride (conflict-free).
// ===========================================================================
#define BKB 64
#define GROW 144                       // bytes per smem row (128 data + 16 pad)
#define GT_BYTES (128 * GROW)          // 18432 per tile
#define GEMM_SMEM (4 * GT_BYTES)       // 73728 (A0,B0,A1,B1)

__global__ __launch_bounds__(256) void gemm_bf16(
    const __nv_bfloat16* __restrict__ A, const __nv_bfloat16* __restrict__ W,
    const float* __restrict__ bias, const float* __restrict__ resid,
    float* __restrict__ C, int M, int N, int K, int round_out)
{
    extern __shared__ char smc[];
    const uint32_t sb = smem_u32(smc);
    const uint32_t sA[2] = { sb,                sb + 2 * GT_BYTES };
    const uint32_t sB[2] = { sb + GT_BYTES,     sb + 3 * GT_BYTES };

    const int tid  = threadIdx.x;
    const int lane = tid & 31;
    const int wid  = tid >> 5;
    const int g    = lane >> 2;
    const int c    = lane & 3;
    const int wm0  = (wid & 3) * 32;
    const int wn0  = (wid >> 2) * 64;
    const int m0   = blockIdx.y * 128;
    const int n0   = blockIdx.x * 128;

    // ldmatrix per-thread address components (constant across loop)
    const uint32_t aOff = (uint32_t)(wm0 + (lane & 15)) * GROW + ((lane >> 4) * 16);
    const uint32_t bOff = (uint32_t)(wn0 + ((lane >> 4) << 3) + (lane & 7)) * GROW
                        + (((lane >> 3) & 1) * 16);

    float acc[2][8][4];
#pragma unroll
    for (int mt = 0; mt < 2; mt++)
#pragma unroll
        for (int nt = 0; nt < 8; nt++)
#pragma unroll
            for (int k = 0; k < 4; k++) acc[mt][nt][k] = 0.f;

    const int nch = K / BKB;           // 16 for K=1024

    auto load_chunk = [&](int i, int st) {
        const __nv_bfloat16* Ag = A + (size_t)m0 * K + i * BKB;
        const __nv_bfloat16* Wg = W + (size_t)n0 * K + i * BKB;
#pragma unroll
        for (int t = 0; t < 4; t++) {
            const int idx = tid + t * 256;
            const int row = idx >> 3;
            const int q   = idx & 7;
            const uint32_t off = (uint32_t)row * GROW + q * 16;
            cp16(sA[st] + off, Ag + (size_t)row * K + q * 8);
            cp16(sB[st] + off, Wg + (size_t)row * K + q * 8);
        }
        CP_COMMIT();
    };

    load_chunk(0, 0);

    for (int i = 0; i < nch; i++) {
        const int st = i & 1;
        if (i + 1 < nch) { load_chunk(i + 1, st ^ 1); CP_WAIT1(); }
        else             { CP_WAIT0(); }
        __syncthreads();

        const uint32_t aBase = sA[st] + aOff;
        const uint32_t bBase = sB[st] + bOff;
#pragma unroll
        for (int kk = 0; kk < 4; kk++) {       // 4 k-steps of 16
            uint32_t a0[4], a1[4];
            LDSM4(a0[0], a0[1], a0[2], a0[3], aBase + kk * 32);
            LDSM4(a1[0], a1[1], a1[2], a1[3], aBase + kk * 32 + 16 * GROW);
            uint32_t bq[4][4];
#pragma unroll
            for (int p = 0; p < 4; p++)
                LDSM4(bq[p][0], bq[p][1], bq[p][2], bq[p][3],
                      bBase + (uint32_t)p * 16 * GROW + kk * 32);
#pragma unroll
            for (int p = 0; p < 4; p++) {
                mma_bf16(acc[0][2 * p    ], a0, bq[p][0], bq[p][1]);
                mma_bf16(acc[0][2 * p + 1], a0, bq[p][2], bq[p][3]);
                mma_bf16(acc[1][2 * p    ], a1, bq[p][0], bq[p][1]);
                mma_bf16(acc[1][2 * p + 1], a1, bq[p][2], bq[p][3]);
            }
        }
        __syncthreads();
    }

    // Epilogue
#pragma unroll
    for (int mt = 0; mt < 2; mt++) {
#pragma unroll
        for (int hrow = 0; hrow < 2; hrow++) {
            const int m = m0 + wm0 + mt * 16 + g + hrow * 8;
#pragma unroll
            for (int nt = 0; nt < 8; nt++) {
                const int col = n0 + wn0 + nt * 8 + c * 2;
                float2 bi = *(const float2*)(bias + col);
                float2 v;
                v.x = acc[mt][nt][hrow * 2 + 0] + bi.x;
                v.y = acc[mt][nt][hrow * 2 + 1] + bi.y;
                if (resid) {
                    float2 r = *(const float2*)(resid + (size_t)m * N + col);
                    v.x += r.x; v.y += r.y;
                }
                if (round_out) { v.x = roundtf(v.x); v.y = roundtf(v.y); }
                *(float2*)(C + (size_t)m * N + col) = v;
            }
        }
    }
}

// ===========================================================================
// Tensor-core flash attention (tf32 mma.sync) — R5-exact except bf16 output.
// Block (qt,h,b): 128 threads / 4 warps; warp w owns q-rows [16w,16w+16).
// ===========================================================================
#define QS_STR 68
#define VS_STR 72
#define KS_OFF 4352                    // 64*68
#define VS_OFF (KS_OFF + 2 * 4352)    // 13056
#define BI_OFF (VS_OFF + 2 * 4608)    // 22272
#define ATTN_SMEM ((BI_OFF + 2 * 128) * 4)   // 90112 bytes

__global__ __launch_bounds__(128) void attn_mma(
    const float* __restrict__ qkv, const float* __restrict__ rpb,
    __nv_bfloat16* __restrict__ obuf)
{
    extern __shared__ float smf[];
    const uint32_t sbase = smem_u32(smf);
    float* Qs = smf;                     // reused as P tile
    uint32_t* PsU = (uint32_t*)Qs;

    const int qt = blockIdx.x;
    const int h  = blockIdx.y;
    const int b  = blockIdx.z;
    const int tid = threadIdx.x;
    const int w    = tid >> 5;
    const int lane = tid & 31;
    const int g    = lane >> 2;
    const int c    = lane & 3;
    const int q0   = qt * 64;
    const int r0   = w * 16 + g;
    const int r1   = r0 + 8;

    // ---- Load Q tile (pre-scaled) ----
    const float CF = SCALE * LOG2E;
#pragma unroll
    for (int t = 0; t < 8; t++) {
        const int idx = tid + t * 128;
        const int r = idx >> 4, q = idx & 15;
        float4 v = *(const float4*)(qkv + (size_t)(b * SS + q0 + r) * D3 + h * HD + q * 4);
        v.x *= CF; v.y *= CF; v.z *= CF; v.w *= CF;
        *(float4*)(Qs + r * QS_STR + q * 4) = v;
    }
    __syncthreads();

    // ---- Extract Q fragments ----
    uint32_t aq[8][4];
#pragma unroll
    for (int kk = 0; kk < 8; kk++) {
        const int col = kk * 8 + c;
        aq[kk][0] = f2tf(Qs[r0 * QS_STR + col    ]);
        aq[kk][1] = f2tf(Qs[r1 * QS_STR + col    ]);
        aq[kk][2] = f2tf(Qs[r0 * QS_STR + col + 4]);
        aq[kk][3] = f2tf(Qs[r1 * QS_STR + col + 4]);
    }
    __syncthreads();   // Qs becomes the P tile

    float m0 = -1e30f, m1 = -1e30f, l0 = 0.f, l1 = 0.f;
    float o[8][4];
#pragma unroll
    for (int nt = 0; nt < 8; nt++)
#pragma unroll
        for (int k = 0; k < 4; k++) o[nt][k] = 0.f;

    auto loadKV = [&](int kt, int st) {
        const float* Kg = qkv + (size_t)(b * SS + kt * 64) * D3 + DD + h * HD;
        const float* Vg = qkv + (size_t)(b * SS + kt * 64) * D3 + 2 * DD + h * HD;
        const uint32_t kbase = sbase + (KS_OFF + st * 4352) * 4u;
        const uint32_t vbase = sbase + (VS_OFF + st * 4608) * 4u;
#pragma unroll
        for (int t = 0; t < 8; t++) {
            const int idx = tid + t * 128;
            const int r = idx >> 4, q = idx & 15;
            cp16(kbase + (uint32_t)(r * QS_STR + q * 4) * 4u, Kg + (size_t)r * D3 + q * 4);
            cp16(vbase + (uint32_t)(r * VS_STR + q * 4) * 4u, Vg + (size_t)r * D3 + q * 4);
        }
        {
            const int delta = tid - 63 + kt * 64 - q0;
            smf[BI_OFF + st * 128 + tid] = rpb[(size_t)(delta + SS - 1) * HH + h] * LOG2E;
        }
        CP_COMMIT();
    };

    loadKV(0, 0);

    for (int kt = 0; kt <= qt; kt++) {
        const int st = kt & 1;
        if (kt < qt) { loadKV(kt + 1, st ^ 1); CP_WAIT1(); }
        else         { CP_WAIT0(); }
        __syncthreads();

        const uint32_t* KsU = (const uint32_t*)(smf + KS_OFF + st * 4352);
        const uint32_t* VsU = (const uint32_t*)(smf + VS_OFF + st * 4608);
        const float* bsp = smf + BI_OFF + st * 128;
        const bool diag = (kt == qt);

        // ---- S = Qhat @ K^T ----
        float s[8][4];
#pragma unroll
        for (int nt = 0; nt < 8; nt++)
#pragma unroll
            for (int k = 0; k < 4; k++) s[nt][k] = 0.f;

#pragma unroll
        for (int kk = 0; kk < 8; kk++) {
            uint32_t bf[8][2];
#pragma unroll
            for (int nt = 0; nt < 8; nt++) {
                const int n = nt * 8 + g;
                bf[nt][0] = KsU[n * QS_STR + kk * 8 + c    ];
                bf[nt][1] = KsU[n * QS_STR + kk * 8 + c + 4];
            }
#pragma unroll
            for (int nt = 0; nt < 8; nt++)
                mma_tf32(s[nt], aq[kk], bf[nt]);
        }

        // ---- bias + causal mask + tile max ----
        float tm0 = -1e30f, tm1 = -1e30f;
#pragma unroll
        for (int nt = 0; nt < 8; nt++) {
            const int col = nt * 8 + c * 2;
            s[nt][0] += bsp[col     - r0 + 63];
            s[nt][1] += bsp[col + 1 - r0 + 63];
            s[nt][2] += bsp[col     - r1 + 63];
            s[nt][3] += bsp[col + 1 - r1 + 63];
            if (diag) {
                if (col     > r0) s[nt][0] = -1e30f;
                if (col + 1 > r0) s[nt][1] = -1e30f;
                if (col     > r1) s[nt][2] = -1e30f;
                if (col + 1 > r1) s[nt][3] = -1e30f;
            }
            tm0 = fmaxf(tm0, fmaxf(s[nt][0], s[nt][1]));
            tm1 = fmaxf(tm1, fmaxf(s[nt][2], s[nt][3]));
        }
        tm0 = fmaxf(tm0, __shfl_xor_sync(0xffffffffu, tm0, 1));
        tm0 = fmaxf(tm0, __shfl_xor_sync(0xffffffffu, tm0, 2));
        tm1 = fmaxf(tm1, __shfl_xor_sync(0xffffffffu, tm1, 1));
        tm1 = fmaxf(tm1, __shfl_xor_sync(0xffffffffu, tm1, 2));

        const float mn0 = fmaxf(m0, tm0);
        const float mn1 = fmaxf(m1, tm1);
        const float alpha0 = ex2f(m0 - mn0);
        const float alpha1 = ex2f(m1 - mn1);
        m0 = mn0; m1 = mn1;

        // ---- P = 2^(s - m); tf32 bits to smem; row sums ----
        float sum0 = 0.f, sum1 = 0.f;
#pragma unroll
        for (int nt = 0; nt < 8; nt++) {
            const int col = nt * 8 + c * 2;
            float p0 = ex2f(s[nt][0] - mn0);
            float p1 = ex2f(s[nt][1] - mn0);
            float p2 = ex2f(s[nt][2] - mn1);
            float p3 = ex2f(s[nt][3] - mn1);
            sum0 += p0 + p1;
            sum1 += p2 + p3;
            *(uint2*)&PsU[r0 * QS_STR + col] = make_uint2(f2tf(p0), f2tf(p1));
            *(uint2*)&PsU[r1 * QS_STR + col] = make_uint2(f2tf(p2), f2tf(p3));
        }
        sum0 += __shfl_xor_sync(0xffffffffu, sum0, 1);
        sum0 += __shfl_xor_sync(0xffffffffu, sum0, 2);
        sum1 += __shfl_xor_sync(0xffffffffu, sum1, 1);
        sum1 += __shfl_xor_sync(0xffffffffu, sum1, 2);
        l0 = l0 * alpha0 + sum0;
        l1 = l1 * alpha1 + sum1;

#pragma unroll
        for (int nt = 0; nt < 8; nt++) {
            o[nt][0] *= alpha0; o[nt][1] *= alpha0;
            o[nt][2] *= alpha1; o[nt][3] *= alpha1;
        }
        __syncwarp();

        // ---- O += P @ V ----
#pragma unroll
        for (int kk = 0; kk < 8; kk++) {
            uint32_t ap[4];
            ap[0] = PsU[r0 * QS_STR + kk * 8 + c    ];
            ap[1] = PsU[r1 * QS_STR + kk * 8 + c    ];
            ap[2] = PsU[r0 * QS_STR + kk * 8 + c + 4];
            ap[3] = PsU[r1 * QS_STR + kk * 8 + c + 4];
            uint32_t bv[8][2];
#pragma unroll
            for (int nt = 0; nt < 8; nt++) {
                const int n = nt * 8 + g;
                bv[nt][0] = VsU[(kk * 8 + c    ) * VS_STR + n];
                bv[nt][1] = VsU[(kk * 8 + c + 4) * VS_STR + n];
            }
#pragma unroll
            for (int nt = 0; nt < 8; nt++)
                mma_tf32(o[nt], ap, bv[nt]);
        }
        __syncthreads();
    }

    // ---- Normalize + write (bf16 for proj GEMM) ----
    const float inv0 = 1.f / l0;
    const float inv1 = 1.f / l1;
    const size_t base0 = (size_t)(b * SS + q0 + r0) * DD + h * HD;
    const size_t base1 = (size_t)(b * SS + q0 + r1) * DD + h * HD;
#pragma unroll
    for (int nt = 0; nt < 8; nt++) {
        const int col = nt * 8 + c * 2;
        __nv_bfloat162 h0 = __floats2bfloat162_rn(o[nt][0] * inv0, o[nt][1] * inv0);
        __nv_bfloat162 h1 = __floats2bfloat162_rn(o[nt][2] * inv1, o[nt][3] * inv1);
        *(__nv_bfloat162*)(obuf + base0 + col) = h0;
        *(__nv_bfloat162*)(obuf + base1 + col) = h1;
    }
}

// ---------------------------------------------------------------------------
// LayerNorm over D=1024
// ---------------------------------------------------------------------------
__global__ __launch_bounds__(256) void layernorm_k(
    const float* __restrict__ y, const float* __restrict__ g,
    const float* __restrict__ bta, float* __restrict__ out)
{
    const int row = blockIdx.x;
    const int t = threadIdx.x;
    const float4 v = *(const float4*)(y + (size_t)row * DD + t * 4);

    float s  = v.x + v.y + v.z + v.w;
    float sq = v.x * v.x + v.y * v.y + v.z * v.z + v.w * v.w;
#pragma unroll
    for (int off = 16; off > 0; off >>= 1) {
        s  += __shfl_xor_sync(0xffffffffu, s, off);
        sq += __shfl_xor_sync(0xffffffffu, sq, off);
    }
    __shared__ float ss[8], sqq[8];
    if ((t & 31) == 0) { ss[t >> 5] = s; sqq[t >> 5] = sq; }
    __syncthreads();
    float tot = 0.f, totq = 0.f;
#pragma unroll
    for (int i = 0; i < 8; i++) { tot += ss[i]; totq += sqq[i]; }
    const float mu  = tot * (1.f / DD);
    const float var = totq * (1.f / DD) - mu * mu;
    const float r   = rsqrtf(var + LN_EPS);

    const float4 gg = *(const float4*)(g + t * 4);
    const float4 bb = *(const float4*)(bta + t * 4);
    float4 o4;
    o4.x = (v.x - mu) * r * gg.x + bb.x;
    o4.y = (v.y - mu) * r * gg.y + bb.y;
    o4.z = (v.z - mu) * r * gg.z + bb.z;
    o4.w = (v.w - mu) * r * gg.w + bb.w;
    *(float4*)(out + (size_t)row * DD + t * 4) = o4;
}

// ---------------------------------------------------------------------------
// Launch
// ---------------------------------------------------------------------------
extern "C" void kernel_launch(void* const* d_in, const int* in_sizes, int n_in,
                              void* d_out, int out_size)
{
    const float* x      = (const float*)d_in[0];
    const float* W_w    = (const float*)d_in[1];
    const float* W_b    = (const float*)d_in[2];
    const float* proj_w = (const float*)d_in[3];
    const float* proj_b = (const float*)d_in[4];
    const float* ln_g   = (const float*)d_in[5];
    const float* ln_b   = (const float*)d_in[6];
    const float* rpb    = (const float*)d_in[7];
    float* out = (float*)d_out;

    float *qkv, *ybuf;
    __nv_bfloat16 *xb, *wb, *pwb, *ob;
    cudaGetSymbolAddress((void**)&qkv, g_qkv);
    cudaGetSymbolAddress((void**)&ybuf, g_y);
    cudaGetSymbolAddress((void**)&xb,  g_xb);
    cudaGetSymbolAddress((void**)&wb,  g_wb);
    cudaGetSymbolAddress((void**)&pwb, g_pwb);
    cudaGetSymbolAddress((void**)&ob,  g_ob);

    cudaFuncSetAttribute(gemm_bf16, cudaFuncAttributeMaxDynamicSharedMemorySize, GEMM_SMEM);
    cudaFuncSetAttribute(attn_mma, cudaFuncAttributeMaxDynamicSharedMemorySize, ATTN_SMEM);

    // 0) Convert inputs to bf16
    cvt_bf16_k<<<(MROWS * DD / 4 + 255) / 256, 256>>>(x, xb, MROWS * DD / 4);
    cvt_bf16_k<<<(D3 * DD / 4 + 255) / 256, 256>>>(W_w, wb, D3 * DD / 4);
    cvt_bf16_k<<<(DD * DD / 4 + 255) / 256, 256>>>(proj_w, pwb, DD * DD / 4);

    // 1) QKV projection (bf16 tensor cores; output tf32-rounded fp32)
    {
        dim3 grid(D3 / 128, MROWS / 128);
        gemm_bf16<<<grid, 256, GEMM_SMEM>>>(xb, wb, W_b, nullptr, qkv, MROWS, D3, DD, 1);
    }

    // 2) Flash attention (tf32 tensor cores, R5-proven; bf16 output)
    {
        dim3 grid(SS / 64, HH, BB);
        attn_mma<<<grid, 128, ATTN_SMEM>>>(qkv, rpb, ob);
    }

    // 3) Output projection + residual (bf16 tensor cores, fp32 resid/out)
    {
        dim3 grid(DD / 128, MROWS / 128);
        gemm_bf16<<<grid, 256, GEMM_SMEM>>>(ob, pwb, proj_b, x, ybuf, MROWS, DD, DD, 0);
    }

    // 4) LayerNorm
    layernorm_k<<<MROWS, 256>>>(ybuf, ln_g, ln_b, out);
}

// round 8
// speedup vs baseline: 2.1950x; 1.3592x over previous
#include <cuda_runtime.h>
#include <cuda_bf16.h>
#include <cstdint>

// Problem constants
#define BB 2
#define SS 2048
#define DD 1024
#define HH 16
#define HD 64
#define D3 3072
#define MROWS (BB * SS)          // 4096
#define SCALE 0.03125f           // 1/sqrt(1024)
#define LOG2E 1.4426950408889634f
#define LN_EPS 1e-5f

// ---------------------------------------------------------------------------
// Scratch (no allocation allowed -> __device__ globals)
// ---------------------------------------------------------------------------
__device__ __nv_bfloat16 g_qkvb[MROWS * D3];   // 24 MB (QKV, bf16)
__device__ float g_y[MROWS * DD];              // 16 MB (proj + residual, fp32)
__device__ __nv_bfloat16 g_xb[MROWS * DD];     //  8 MB (x, bf16)
__device__ __nv_bfloat16 g_wb[D3 * DD];        //  6 MB (W_w, bf16)
__device__ __nv_bfloat16 g_pwb[DD * DD];       //  2 MB (proj_w, bf16)
__device__ __nv_bfloat16 g_ob[MROWS * DD];     //  8 MB (attention out, bf16)

// ---------------------------------------------------------------------------
// Portable helpers (sm_80+ only)
// ---------------------------------------------------------------------------
__device__ __forceinline__ uint32_t smem_u32(const void* p) {
    uint32_t a;
    asm("{ .reg .u64 t; cvta.to.shared.u64 t, %1; cvt.u32.u64 %0, t; }"
        : "=r"(a) : "l"(p));
    return a;
}

__device__ __forceinline__ void cp16(uint32_t dst, const void* src) {
    asm volatile("cp.async.ca.shared.global [%0], [%1], 16;"
                 :: "r"(dst), "l"(src) : "memory");
}
#define CP_COMMIT() asm volatile("cp.async.commit_group;" ::: "memory")
#define CP_WAIT1()  asm volatile("cp.async.wait_group 1;" ::: "memory")
#define CP_WAIT0()  asm volatile("cp.async.wait_group 0;" ::: "memory")

__device__ __forceinline__ float ex2f(float x) {
    float r;
    asm("ex2.approx.f32 %0, %1;" : "=f"(r) : "f"(x));
    return r;
}

__device__ __forceinline__ void mma_bf16(
    float* c, const uint32_t* a, uint32_t b0, uint32_t b1)
{
    asm volatile(
        "mma.sync.aligned.m16n8k16.row.col.f32.bf16.bf16.f32 "
        "{%0,%1,%2,%3}, {%4,%5,%6,%7}, {%8,%9}, {%0,%1,%2,%3};"
        : "+f"(c[0]), "+f"(c[1]), "+f"(c[2]), "+f"(c[3])
        : "r"(a[0]), "r"(a[1]), "r"(a[2]), "r"(a[3]),
          "r"(b0), "r"(b1));
}

#define LDSM4(r0, r1, r2, r3, addr) \
    asm volatile("ldmatrix.sync.aligned.m8n8.x4.shared.b16 {%0,%1,%2,%3}, [%4];" \
        : "=r"(r0), "=r"(r1), "=r"(r2), "=r"(r3) : "r"(addr))

#define LDSM4T(r0, r1, r2, r3, addr) \
    asm volatile("ldmatrix.sync.aligned.m8n8.x4.trans.shared.b16 {%0,%1,%2,%3}, [%4];" \
        : "=r"(r0), "=r"(r1), "=r"(r2), "=r"(r3) : "r"(addr))

__device__ __forceinline__ uint32_t pack_bf16x2(float lo, float hi) {
    __nv_bfloat162 h = __floats2bfloat162_rn(lo, hi);
    return *(uint32_t*)&h;
}

// ---------------------------------------------------------------------------
// fp32 -> bf16 conversion (vectorized)
// ---------------------------------------------------------------------------
__global__ __launch_bounds__(256) void cvt_bf16_k(
    const float* __restrict__ in, __nv_bfloat16* __restrict__ out, int n4)
{
    const int i = blockIdx.x * 256 + threadIdx.x;
    if (i < n4) {
        float4 v = *(const float4*)(in + (size_t)i * 4);
        uint2 u;
        u.x = pack_bf16x2(v.x, v.y);
        u.y = pack_bf16x2(v.z, v.w);
        *(uint2*)(out + (size_t)i * 4) = u;
    }
}

// ===========================================================================
// BF16 mma.sync GEMM: out = A[M,K] @ W[N,K]^T + bias (+ resid)
// Output to EITHER C (fp32) or Cb (bf16) — the other must be null.
// CTA 128x128, BK=64, 8 warps (4M x 2N), ldmatrix.x4, 144B rows.
// ===========================================================================
#define BKB 64
#define GROW 144
#define GT_BYTES (128 * GROW)          // 18432 per tile
#define GEMM_SMEM (4 * GT_BYTES)       // 73728

__global__ __launch_bounds__(256) void gemm_bf16(
    const __nv_bfloat16* __restrict__ A, const __nv_bfloat16* __restrict__ W,
    const float* __restrict__ bias, const float* __restrict__ resid,
    float* __restrict__ C, __nv_bfloat16* __restrict__ Cb,
    int M, int N, int K)
{
    extern __shared__ char smc[];
    const uint32_t sb = smem_u32(smc);
    const uint32_t sA[2] = { sb,            sb + 2 * GT_BYTES };
    const uint32_t sB[2] = { sb + GT_BYTES, sb + 3 * GT_BYTES };

    const int tid  = threadIdx.x;
    const int lane = tid & 31;
    const int wid  = tid >> 5;
    const int g    = lane >> 2;
    const int c    = lane & 3;
    const int wm0  = (wid & 3) * 32;
    const int wn0  = (wid >> 2) * 64;
    const int m0   = blockIdx.y * 128;
    const int n0   = blockIdx.x * 128;

    const uint32_t aOff = (uint32_t)(wm0 + (lane & 15)) * GROW + ((lane >> 4) * 16);
    const uint32_t bOff = (uint32_t)(wn0 + ((lane >> 4) << 3) + (lane & 7)) * GROW
                        + (((lane >> 3) & 1) * 16);

    float acc[2][8][4];
#pragma unroll
    for (int mt = 0; mt < 2; mt++)
#pragma unroll
        for (int nt = 0; nt < 8; nt++)
#pragma unroll
            for (int k = 0; k < 4; k++) acc[mt][nt][k] = 0.f;

    const int nch = K / BKB;

    auto load_chunk = [&](int i, int st) {
        const __nv_bfloat16* Ag = A + (size_t)m0 * K + i * BKB;
        const __nv_bfloat16* Wg = W + (size_t)n0 * K + i * BKB;
#pragma unroll
        for (int t = 0; t < 4; t++) {
            const int idx = tid + t * 256;
            const int row = idx >> 3;
            const int q   = idx & 7;
            const uint32_t off = (uint32_t)row * GROW + q * 16;
            cp16(sA[st] + off, Ag + (size_t)row * K + q * 8);
            cp16(sB[st] + off, Wg + (size_t)row * K + q * 8);
        }
        CP_COMMIT();
    };

    load_chunk(0, 0);

    for (int i = 0; i < nch; i++) {
        const int st = i & 1;
        if (i + 1 < nch) { load_chunk(i + 1, st ^ 1); CP_WAIT1(); }
        else             { CP_WAIT0(); }
        __syncthreads();

        const uint32_t aBase = sA[st] + aOff;
        const uint32_t bBase = sB[st] + bOff;
#pragma unroll
        for (int kk = 0; kk < 4; kk++) {
            uint32_t a0[4], a1[4];
            LDSM4(a0[0], a0[1], a0[2], a0[3], aBase + kk * 32);
            LDSM4(a1[0], a1[1], a1[2], a1[3], aBase + kk * 32 + 16 * GROW);
            uint32_t bq[4][4];
#pragma unroll
            for (int p = 0; p < 4; p++)
                LDSM4(bq[p][0], bq[p][1], bq[p][2], bq[p][3],
                      bBase + (uint32_t)p * 16 * GROW + kk * 32);
#pragma unroll
            for (int p = 0; p < 4; p++) {
                mma_bf16(acc[0][2 * p    ], a0, bq[p][0], bq[p][1]);
                mma_bf16(acc[0][2 * p + 1], a0, bq[p][2], bq[p][3]);
                mma_bf16(acc[1][2 * p    ], a1, bq[p][0], bq[p][1]);
                mma_bf16(acc[1][2 * p + 1], a1, bq[p][2], bq[p][3]);
            }
        }
        __syncthreads();
    }

    // Epilogue
#pragma unroll
    for (int mt = 0; mt < 2; mt++) {
#pragma unroll
        for (int hrow = 0; hrow < 2; hrow++) {
            const int m = m0 + wm0 + mt * 16 + g + hrow * 8;
#pragma unroll
            for (int nt = 0; nt < 8; nt++) {
                const int col = n0 + wn0 + nt * 8 + c * 2;
                float2 bi = *(const float2*)(bias + col);
                float2 v;
                v.x = acc[mt][nt][hrow * 2 + 0] + bi.x;
                v.y = acc[mt][nt][hrow * 2 + 1] + bi.y;
                if (resid) {
                    float2 r = *(const float2*)(resid + (size_t)m * N + col);
                    v.x += r.x; v.y += r.y;
                }
                if (Cb) {
                    uint32_t h = pack_bf16x2(v.x, v.y);
                    *(uint32_t*)(Cb + (size_t)m * N + col) = h;
                } else {
                    *(float2*)(C + (size_t)m * N + col) = v;
                }
            }
        }
    }
}

// ===========================================================================
// BF16 tensor-core flash attention, causal + rel-pos bias.
// Block (qt,h,b): 128 threads / 4 warps; warp w owns q-rows [16w,16w+16).
// All fragments via ldmatrix; scale folded into bias FMA.
// ===========================================================================
#define AROW 144                         // smem row stride bytes (128 data + 16)
#define QP_OFF 0                         // Q tile, reused as P tile (9216 B)
#define K_OFF  (64 * AROW)               // 9216, 2 stages
#define V_OFF  (K_OFF + 2 * 64 * AROW)   // 27648, 2 stages
#define BIA_OFF (V_OFF + 2 * 64 * AROW)  // 46080, 2 x 128 floats
#define ATTN_SMEM (BIA_OFF + 2 * 128 * 4)  // 47104 bytes

__global__ __launch_bounds__(128) void attn_bf16(
    const __nv_bfloat16* __restrict__ qkv, const float* __restrict__ rpb,
    __nv_bfloat16* __restrict__ obuf)
{
    extern __shared__ char smc[];
    const uint32_t sb = smem_u32(smc);

    const int qt = blockIdx.x;
    const int h  = blockIdx.y;
    const int b  = blockIdx.z;
    const int tid = threadIdx.x;
    const int w    = tid >> 5;
    const int lane = tid & 31;
    const int g    = lane >> 2;
    const int c    = lane & 3;
    const int q0   = qt * 64;
    const int r0   = w * 16 + g;
    const int r1   = r0 + 8;
    const float CF = SCALE * LOG2E;

    // ---- Load Q tile (raw bf16, plain loads) ----
    {
        const __nv_bfloat16* Qg = qkv + (size_t)(b * SS + q0) * D3 + h * HD;
#pragma unroll
        for (int t = 0; t < 4; t++) {
            const int idx = tid + t * 128;
            const int row = idx >> 3, q = idx & 7;
            uint4 v = *(const uint4*)(Qg + (size_t)row * D3 + q * 8);
            *(uint4*)(smc + QP_OFF + row * AROW + q * 16) = v;
        }
    }
    __syncthreads();

    // ---- Extract Q fragments ----
    const uint32_t fragOff = (uint32_t)(lane & 15) * AROW + ((lane >> 4) * 16);
    const uint32_t wrowOff = (uint32_t)(w * 16) * AROW;
    uint32_t aq[4][4];
#pragma unroll
    for (int ks = 0; ks < 4; ks++)
        LDSM4(aq[ks][0], aq[ks][1], aq[ks][2], aq[ks][3],
              sb + QP_OFF + wrowOff + fragOff + ks * 32);
    __syncthreads();   // Qs becomes the P tile

    float m0 = -1e30f, m1 = -1e30f, l0 = 0.f, l1 = 0.f;
    float o[8][4];
#pragma unroll
    for (int nt = 0; nt < 8; nt++)
#pragma unroll
        for (int k = 0; k < 4; k++) o[nt][k] = 0.f;

    const uint32_t bOffK = (uint32_t)(((lane >> 4) << 3) + (lane & 7)) * AROW
                         + (((lane >> 3) & 1) * 16);
    const uint32_t vOffT = (uint32_t)(lane & 15) * AROW + ((lane >> 4) * 16);

    auto loadKV = [&](int kt, int st) {
        const __nv_bfloat16* Kg = qkv + (size_t)(b * SS + kt * 64) * D3 + DD + h * HD;
        const __nv_bfloat16* Vg = qkv + (size_t)(b * SS + kt * 64) * D3 + 2 * DD + h * HD;
        const uint32_t kbase = sb + K_OFF + st * (64 * AROW);
        const uint32_t vbase = sb + V_OFF + st * (64 * AROW);
#pragma unroll
        for (int t = 0; t < 4; t++) {
            const int idx = tid + t * 128;
            const int row = idx >> 3, q = idx & 7;
            const uint32_t off = (uint32_t)row * AROW + q * 16;
            cp16(kbase + off, Kg + (size_t)row * D3 + q * 8);
            cp16(vbase + off, Vg + (size_t)row * D3 + q * 8);
        }
        {
            const int delta = tid - 63 + kt * 64 - q0;
            ((float*)(smc + BIA_OFF))[st * 128 + tid] =
                rpb[(size_t)(delta + SS - 1) * HH + h] * LOG2E;
        }
        CP_COMMIT();
    };

    loadKV(0, 0);

    for (int kt = 0; kt <= qt; kt++) {
        const int st = kt & 1;
        if (kt < qt) { loadKV(kt + 1, st ^ 1); CP_WAIT1(); }
        else         { CP_WAIT0(); }
        __syncthreads();

        const uint32_t kbase = sb + K_OFF + st * (64 * AROW);
        const uint32_t vbase = sb + V_OFF + st * (64 * AROW);
        const float* bsp = (const float*)(smc + BIA_OFF) + st * 128;
        const bool diag = (kt == qt);

        // ---- S = Q @ K^T (raw), 32 MMAs ----
        float s[8][4];
#pragma unroll
        for (int nt = 0; nt < 8; nt++)
#pragma unroll
            for (int k = 0; k < 4; k++) s[nt][k] = 0.f;

#pragma unroll
        for (int ks = 0; ks < 4; ks++) {
            uint32_t bq[4][4];
#pragma unroll
            for (int p = 0; p < 4; p++)
                LDSM4(bq[p][0], bq[p][1], bq[p][2], bq[p][3],
                      kbase + bOffK + (uint32_t)p * 16 * AROW + ks * 32);
#pragma unroll
            for (int p = 0; p < 4; p++) {
                mma_bf16(s[2 * p    ], aq[ks], bq[p][0], bq[p][1]);
                mma_bf16(s[2 * p + 1], aq[ks], bq[p][2], bq[p][3]);
            }
        }

        // ---- scale + bias (one FMA) + causal mask + tile max ----
        float tm0 = -1e30f, tm1 = -1e30f;
#pragma unroll
        for (int nt = 0; nt < 8; nt++) {
            const int col = nt * 8 + c * 2;
            s[nt][0] = fmaf(s[nt][0], CF, bsp[col     - r0 + 63]);
            s[nt][1] = fmaf(s[nt][1], CF, bsp[col + 1 - r0 + 63]);
            s[nt][2] = fmaf(s[nt][2], CF, bsp[col     - r1 + 63]);
            s[nt][3] = fmaf(s[nt][3], CF, bsp[col + 1 - r1 + 63]);
            if (diag) {
                if (col     > r0) s[nt][0] = -1e30f;
                if (col + 1 > r0) s[nt][1] = -1e30f;
                if (col     > r1) s[nt][2] = -1e30f;
                if (col + 1 > r1) s[nt][3] = -1e30f;
            }
            tm0 = fmaxf(tm0, fmaxf(s[nt][0], s[nt][1]));
            tm1 = fmaxf(tm1, fmaxf(s[nt][2], s[nt][3]));
        }
        tm0 = fmaxf(tm0, __shfl_xor_sync(0xffffffffu, tm0, 1));
        tm0 = fmaxf(tm0, __shfl_xor_sync(0xffffffffu, tm0, 2));
        tm1 = fmaxf(tm1, __shfl_xor_sync(0xffffffffu, tm1, 1));
        tm1 = fmaxf(tm1, __shfl_xor_sync(0xffffffffu, tm1, 2));

        const float mn0 = fmaxf(m0, tm0);
        const float mn1 = fmaxf(m1, tm1);
        const float alpha0 = ex2f(m0 - mn0);
        const float alpha1 = ex2f(m1 - mn1);
        m0 = mn0; m1 = mn1;

        // ---- P = 2^(s-m) -> bf16x2 to P tile; row sums ----
        uint32_t* Pw = (uint32_t*)(smc + QP_OFF);
        float sum0 = 0.f, sum1 = 0.f;
#pragma unroll
        for (int nt = 0; nt < 8; nt++) {
            float p0 = ex2f(s[nt][0] - mn0);
            float p1 = ex2f(s[nt][1] - mn0);
            float p2 = ex2f(s[nt][2] - mn1);
            float p3 = ex2f(s[nt][3] - mn1);
            sum0 += p0 + p1;
            sum1 += p2 + p3;
            Pw[r0 * 36 + nt * 4 + c] = pack_bf16x2(p0, p1);
            Pw[r1 * 36 + nt * 4 + c] = pack_bf16x2(p2, p3);
        }
        sum0 += __shfl_xor_sync(0xffffffffu, sum0, 1);
        sum0 += __shfl_xor_sync(0xffffffffu, sum0, 2);
        sum1 += __shfl_xor_sync(0xffffffffu, sum1, 1);
        sum1 += __shfl_xor_sync(0xffffffffu, sum1, 2);
        l0 = l0 * alpha0 + sum0;
        l1 = l1 * alpha1 + sum1;

#pragma unroll
        for (int nt = 0; nt < 8; nt++) {
            o[nt][0] *= alpha0; o[nt][1] *= alpha0;
            o[nt][2] *= alpha1; o[nt][3] *= alpha1;
        }
        __syncwarp();

        // ---- O += P @ V (A from P tile, B via ldmatrix.trans on V) ----
#pragma unroll
        for (int ks = 0; ks < 4; ks++) {
            uint32_t ap[4];
            LDSM4(ap[0], ap[1], ap[2], ap[3],
                  sb + QP_OFF + wrowOff + fragOff + ks * 32);
            uint32_t bv[4][4];
#pragma unroll
            for (int p = 0; p < 4; p++)
                LDSM4T(bv[p][0], bv[p][1], bv[p][2], bv[p][3],
                       vbase + vOffT + (uint32_t)ks * 16 * AROW + p * 32);
#pragma unroll
            for (int p = 0; p < 4; p++) {
                mma_bf16(o[2 * p    ], ap, bv[p][0], bv[p][1]);
                mma_bf16(o[2 * p + 1], ap, bv[p][2], bv[p][3]);
            }
        }
        __syncthreads();
    }

    // ---- Normalize + write bf16 ----
    const float inv0 = 1.f / l0;
    const float inv1 = 1.f / l1;
    const size_t base0 = (size_t)(b * SS + q0 + r0) * DD + h * HD;
    const size_t base1 = (size_t)(b * SS + q0 + r1) * DD + h * HD;
#pragma unroll
    for (int nt = 0; nt < 8; nt++) {
        const int col = nt * 8 + c * 2;
        *(uint32_t*)(obuf + base0 + col) = pack_bf16x2(o[nt][0] * inv0, o[nt][1] * inv0);
        *(uint32_t*)(obuf + base1 + col) = pack_bf16x2(o[nt][2] * inv1, o[nt][3] * inv1);
    }
}

// ---------------------------------------------------------------------------
// LayerNorm over D=1024
// ---------------------------------------------------------------------------
__global__ __launch_bounds__(256) void layernorm_k(
    const float* __restrict__ y, const float* __restrict__ g,
    const float* __restrict__ bta, float* __restrict__ out)
{
    const int row = blockIdx.x;
    const int t = threadIdx.x;
    const float4 v = *(const float4*)(y + (size_t)row * DD + t * 4);

    float s  = v.x + v.y + v.z + v.w;
    float sq = v.x * v.x + v.y * v.y + v.z * v.z + v.w * v.w;
#pragma unroll
    for (int off = 16; off > 0; off >>= 1) {
        s  += __shfl_xor_sync(0xffffffffu, s, off);
        sq += __shfl_xor_sync(0xffffffffu, sq, off);
    }
    __shared__ float ss[8], sqq[8];
    if ((t & 31) == 0) { ss[t >> 5] = s; sqq[t >> 5] = sq; }
    __syncthreads();
    float tot = 0.f, totq = 0.f;
#pragma unroll
    for (int i = 0; i < 8; i++) { tot += ss[i]; totq += sqq[i]; }
    const float mu  = tot * (1.f / DD);
    const float var = totq * (1.f / DD) - mu * mu;
    const float r   = rsqrtf(var + LN_EPS);

    const float4 gg = *(const float4*)(g + t * 4);
    const float4 bb = *(const float4*)(bta + t * 4);
    float4 o4;
    o4.x = (v.x - mu) * r * gg.x + bb.x;
    o4.y = (v.y - mu) * r * gg.y + bb.y;
    o4.z = (v.z - mu) * r * gg.z + bb.z;
    o4.w = (v.w - mu) * r * gg.w + bb.w;
    *(float4*)(out + (size_t)row * DD + t * 4) = o4;
}

// ---------------------------------------------------------------------------
// Launch
// ---------------------------------------------------------------------------
extern "C" void kernel_launch(void* const* d_in, const int* in_sizes, int n_in,
                              void* d_out, int out_size)
{
    const float* x      = (const float*)d_in[0];
    const float* W_w    = (const float*)d_in[1];
    const float* W_b    = (const float*)d_in[2];
    const float* proj_w = (const float*)d_in[3];
    const float* proj_b = (const float*)d_in[4];
    const float* ln_g   = (const float*)d_in[5];
    const float* ln_b   = (const float*)d_in[6];
    const float* rpb    = (const float*)d_in[7];
    float* out = (float*)d_out;

    float *ybuf;
    __nv_bfloat16 *qkvb, *xb, *wb, *pwb, *ob;
    cudaGetSymbolAddress((void**)&qkvb, g_qkvb);
    cudaGetSymbolAddress((void**)&ybuf, g_y);
    cudaGetSymbolAddress((void**)&xb,  g_xb);
    cudaGetSymbolAddress((void**)&wb,  g_wb);
    cudaGetSymbolAddress((void**)&pwb, g_pwb);
    cudaGetSymbolAddress((void**)&ob,  g_ob);

    cudaFuncSetAttribute(gemm_bf16, cudaFuncAttributeMaxDynamicSharedMemorySize, GEMM_SMEM);
    cudaFuncSetAttribute(attn_bf16, cudaFuncAttributeMaxDynamicSharedMemorySize, ATTN_SMEM);

    // 0) Convert inputs to bf16
    cvt_bf16_k<<<(MROWS * DD / 4 + 255) / 256, 256>>>(x, xb, MROWS * DD / 4);
    cvt_bf16_k<<<(D3 * DD / 4 + 255) / 256, 256>>>(W_w, wb, D3 * DD / 4);
    cvt_bf16_k<<<(DD * DD / 4 + 255) / 256, 256>>>(proj_w, pwb, DD * DD / 4);

    // 1) QKV projection -> bf16 output
    {
        dim3 grid(D3 / 128, MROWS / 128);
        gemm_bf16<<<grid, 256, GEMM_SMEM>>>(xb, wb, W_b, nullptr,
                                            nullptr, qkvb, MROWS, D3, DD);
    }

    // 2) Flash attention (bf16 tensor cores + ldmatrix)
    {
        dim3 grid(SS / 64, HH, BB);
        attn_bf16<<<grid, 128, ATTN_SMEM>>>(qkvb, rpb, ob);
    }

    // 3) Output projection + residual -> fp32
    {
        dim3 grid(DD / 128, MROWS / 128);
        gemm_bf16<<<grid, 256, GEMM_SMEM>>>(ob, pwb, proj_b, x,
                                            ybuf, nullptr, MROWS, DD, DD);
    }

    // 4) LayerNorm
    layernorm_k<<<MROWS, 256>>>(ybuf, ln_g, ln_b, out);
}